// round 7
// baseline (speedup 1.0000x reference)
#include <cuda_runtime.h>
#include <math.h>

// RandomLowRes2D fused kernel, v5: NT=128 (6 CTAs/SM), lane-major smem,
// vectorized blur loads+stores, inline downsample coords, 2KB pos LUT.

#define HDIM 512
#define TW   8            // lanes (cross-axis) per CTA
#define HALO 16
#define AS   548          // A row stride; 548 % 32 == 4, 16B aligned
#define SP   516          // S/LOW row stride; 516 % 32 == 4, 16B aligned
#define NT   128

__device__ __forceinline__ int refl(int t) {
    t = (t < 0) ? (-1 - t) : t;
    return (t >= HDIM) ? (2 * HDIM - 1 - t) : t;
}

// Blur A(+halo, lane-major) -> S. Vec4 window loads, symmetric taps, vec4 stores.
template<int R, int UN>
__device__ __forceinline__ void blur_slab(const float* __restrict__ A,
                                          float* __restrict__ S,
                                          const float* __restrict__ w,
                                          float inv_wsum, int tid)
{
    constexpr int LO   = -(((R + 3) / 4) * 4);
    constexpr int NVEC = (UN - 1 + R - LO) / 4 + 1;
    float wr[R + 1];
    #pragma unroll
    for (int k = 0; k <= R; k++) wr[k] = w[15 - R + k] * inv_wsum;

    for (int task = tid; task < (HDIM / UN) * TW; task += NT) {
        int l  = task & (TW - 1);
        int p0 = (task >> 3) * UN;
        const float4* src = (const float4*)(A + l * AS + HALO + p0 + LO);
        float win[4 * NVEC];
        #pragma unroll
        for (int v = 0; v < NVEC; v++) {
            float4 t4 = src[v];
            win[4*v+0] = t4.x; win[4*v+1] = t4.y;
            win[4*v+2] = t4.z; win[4*v+3] = t4.w;
        }
        float4* so = (float4*)(S + l * SP + p0);
        #pragma unroll
        for (int uv = 0; uv < UN / 4; uv++) {
            float4 r;
            #pragma unroll
            for (int q = 0; q < 4; q++) {
                int u = 4 * uv + q;
                float acc = wr[R] * win[u - LO];
                #pragma unroll
                for (int k = 0; k < R; k++)
                    acc += wr[k] * (win[u - R + k - LO] + win[u + R - k - LO]);
                ((float*)&r)[q] = acc;
            }
            so[uv] = r;
        }
    }
}

__global__ __launch_bounds__(NT, 6)
void lowres_kernel(const float* __restrict__ x,
                   const float* __restrict__ resolution,
                   const int*   __restrict__ axis,
                   const float* __restrict__ gap,
                   float* __restrict__ out)
{
    extern __shared__ float dynsm[];
    float* A    = dynsm;                       // [TW][AS] input + halo
    float* S    = dynsm + TW * AS;             // [TW][SP] blurred
    float* pos2 = dynsm + TW * AS + TW * SP;   // [HDIM] upsample positions
    float* w    = pos2 + HDIM;                 // [32] raw weights

    const int img  = blockIdx.y;
    const int tile = blockIdx.x;
    const int tid  = threadIdx.x;

    const float res = resolution[img];
    const int   ax  = axis[img];
    const float sig = fmaxf(res * gap[img] * 0.42466090014400953f, 1e-6f);
    const int   R   = (sig < 0.18f) ? 0 : (sig < 0.6f) ? 3 : (sig < 1.4f) ? 7 : 15;

    const int   n_low = (int)fmaxf(floorf(512.0f / res), 1.0f);
    const float nl1   = (float)(n_low - 1);

    if (tid < 31) {
        float e = (float)(tid - 15) / sig;
        w[tid] = expf(-0.5f * e * e);
    }
    for (int i = tid; i < HDIM; i += NT)
        pos2[i] = fminf((float)i / res, nl1);   // true division as reference

    const int base = tile * TW;
    const size_t ib = (size_t)img * HDIM * HDIM;
    const float* ip = x + ib;
    float*       op = out + ib;

    // ---- load slab into lane-major A, plus reflected halo ----
    if (ax == 0) {
        const float4* ip4 = (const float4*)ip;
        for (int idx = tid; idx < HDIM * 2; idx += NT) {
            int l4 = idx & 1;
            int p  = idx >> 1;
            float4 v = ip4[p * (HDIM / 4) + (base >> 2) + l4];
            float* dst = A + (4 * l4) * AS + HALO + p;
            dst[0] = v.x; dst[AS] = v.y; dst[2 * AS] = v.z; dst[3 * AS] = v.w;
        }
    } else {
        for (int idx = tid; idx < TW * (HDIM / 4); idx += NT) {
            int v = idx & 127;
            int l = idx >> 7;
            float4 t = *(const float4*)(ip + (size_t)(base + l) * HDIM + 4 * v);
            *(float4*)(A + l * AS + HALO + 4 * v) = t;
        }
    }
    for (int idx = tid; idx < 2 * HALO * TW; idx += NT) {  // 256 halo elems
        int l = idx & (TW - 1);
        int h = idx >> 3;
        int t = (h < HALO) ? (h - HALO) : (HDIM + h - HALO);
        int rt = refl(t);
        float val = (ax == 0) ? ip[rt * HDIM + base + l]
                              : ip[(size_t)(base + l) * HDIM + rt];
        A[l * AS + HALO + t] = val;
    }
    __syncthreads();

    float inv_wsum = 1.0f;
    if (R > 0) {
        float s = 0.f;
        #pragma unroll
        for (int k = 0; k < 31; k++) s += w[k];
        inv_wsum = 1.0f / s;
    }

    // ---- blur ----
    if      (R == 3)  blur_slab<3, 8>(A, S, w, inv_wsum, tid);
    else if (R == 7)  blur_slab<7, 8>(A, S, w, inv_wsum, tid);
    else if (R == 15) blur_slab<15, 8>(A, S, w, inv_wsum, tid);
    __syncthreads();

    // ---- downsample: SRC -> LOW (4 j per thread, inline coords, vec4 store) ----
    const float* SRC = (R > 0) ? S : (A + HALO);
    const int    SST = (R > 0) ? SP : AS;
    float* LOW = (R > 0) ? A : S;              // stride SP
    const int ngrp = (n_low + 3) >> 2;
    for (int idx = tid; idx < ngrp * TW; idx += NT) {
        int l  = idx & (TW - 1);
        int j0 = (idx >> 3) << 2;
        const float* sr = SRC + l * SST;
        float4 r;
        #pragma unroll
        for (int q = 0; q < 4; q++) {
            float pos = fminf((float)(j0 + q) * res, 511.0f);
            float lo  = floorf(pos);
            float f   = pos - lo;
            int p1 = (int)lo;
            int p2 = min(p1 + 1, HDIM - 1);
            ((float*)&r)[q] = sr[p1] * (1.0f - f) + sr[p2] * f;
        }
        *(float4*)(LOW + l * SP + j0) = r;
    }
    __syncthreads();

    // ---- upsample + float4 gmem stores ----
    if (ax == 0) {
        for (int idx = tid; idx < HDIM * 2; idx += NT) {
            int l4 = idx & 1;
            int i  = idx >> 1;
            float p2v = pos2[i];
            float l2  = floorf(p2v);
            float f   = p2v - l2;
            int j1 = min((int)l2, n_low - 1);
            int j2 = min(j1 + 1, n_low - 1);
            float omf = 1.0f - f;
            const float* L0 = LOW + (4 * l4) * SP;
            float4 r;
            r.x = L0[j1] * omf          + L0[j2] * f;
            r.y = L0[SP + j1] * omf     + L0[SP + j2] * f;
            r.z = L0[2 * SP + j1] * omf + L0[2 * SP + j2] * f;
            r.w = L0[3 * SP + j1] * omf + L0[3 * SP + j2] * f;
            *(float4*)(op + i * HDIM + base + 4 * l4) = r;
        }
    } else {
        for (int idx = tid; idx < TW * (HDIM / 4); idx += NT) {
            int v = idx & 127;
            int l = idx >> 7;
            const float* Lrow = LOW + l * SP;
            const float4 pv = *(const float4*)(pos2 + 4 * v);
            float4 r;
            #pragma unroll
            for (int q = 0; q < 4; q++) {
                float p2v = ((const float*)&pv)[q];
                float l2  = floorf(p2v);
                float f   = p2v - l2;
                int j1 = min((int)l2, n_low - 1);
                int j2 = min(j1 + 1, n_low - 1);
                ((float*)&r)[q] = Lrow[j1] * (1.0f - f) + Lrow[j2] * f;
            }
            *(float4*)(op + (size_t)(base + l) * HDIM + 4 * v) = r;
        }
    }
}

extern "C" void kernel_launch(void* const* d_in, const int* in_sizes, int n_in,
                              void* d_out, int out_size)
{
    const float* x   = (const float*)d_in[0];
    const float* res = (const float*)d_in[1];
    const int*   ax  = (const int*)d_in[2];
    const float* gp  = (const float*)d_in[3];
    float* out = (float*)d_out;

    const int n_img = in_sizes[1];   // 64
    // A + S + pos2 + w : (8*548 + 8*516 + 512 + 32) * 4 = 36224 B
    const size_t smem = (size_t)(TW * AS + TW * SP + HDIM + 32) * sizeof(float);

    cudaFuncSetAttribute(lowres_kernel,
                         cudaFuncAttributeMaxDynamicSharedMemorySize, (int)smem);

    dim3 grid(HDIM / TW, n_img);     // 64 x 64 = 4096 CTAs
    lowres_kernel<<<grid, NT, smem>>>(x, res, ax, gp, out);
}

// round 8
// speedup vs baseline: 1.1766x; 1.1766x over previous
#include <cuda_runtime.h>
#include <cuda_fp16.h>
#include <math.h>

// RandomLowRes2D fused kernel, v6: blur fused with downsample (blur evaluated
// only at needed taps), fp16 low-res buffer, 8 CTAs/SM, interleaved images.

#define HDIM 512
#define TW   8            // lanes (cross-axis) per CTA
#define HALO 16
#define AS   548          // A row stride; 548 % 32 == 4
#define LH   520          // LOW row stride in halfs; word-stride 260 % 32 == 4
#define NT   128

__device__ __forceinline__ int refl(int t) {
    t = (t < 0) ? (-1 - t) : t;
    return (t >= HDIM) ? (2 * HDIM - 1 - t) : t;
}

// Fused blur+downsample: for each low row j, evaluate truncated Gaussian blur
// at rows p1, p1+1 (shared scalar-load sweep) and lerp. Accumulators fp32.
template<int R>
__device__ __forceinline__ void blur_down(const float* __restrict__ A,
                                          __half* __restrict__ LOW,
                                          const float* __restrict__ w,
                                          float inv_wsum, float res,
                                          int n_low, int tid)
{
    float wr[R + 1];
    if (R == 0) {
        wr[0] = 1.0f;
    } else {
        #pragma unroll
        for (int k = 0; k <= R; k++) wr[k] = w[15 - R + k] * inv_wsum;
    }
    const int ntask = n_low * TW;
    for (int task = tid; task < ntask; task += NT) {
        int l = task & (TW - 1);
        int j = task >> 3;
        float pos = fminf((float)j * res, 511.0f);
        float lof = floorf(pos);
        float fr  = pos - lof;
        int   p1  = (int)lof;
        const float* Ar = A + l * AS + HALO + p1 - R;
        float a0 = 0.f, a1 = 0.f;
        #pragma unroll
        for (int k = 0; k <= 2 * R + 1; k++) {
            float v = Ar[k];
            if (k <= 2 * R) {
                int s0 = (k <= R) ? k : 2 * R - k;
                a0 += wr[s0] * v;
            }
            if (k >= 1) {
                int km = k - 1;
                int s1 = (km <= R) ? km : 2 * R - km;
                a1 += wr[s1] * v;
            }
        }
        // p1+1 clamp: when p1==511 fr==0 so a1 (halo data, finite) is unused.
        LOW[l * LH + j] = __float2half(a0 * (1.0f - fr) + a1 * fr);
    }
}

__global__ __launch_bounds__(NT, 8)
void lowres_kernel(const float* __restrict__ x,
                   const float* __restrict__ resolution,
                   const int*   __restrict__ axis,
                   const float* __restrict__ gap,
                   float* __restrict__ out)
{
    extern __shared__ float dynsm[];
    float*  A    = dynsm;                              // [TW][AS] fp32 + halo
    __half* LOW  = (__half*)(dynsm + TW * AS);         // [TW][LH] fp16
    float*  pos2 = dynsm + TW * AS + (TW * LH) / 2;    // [HDIM] upsample pos
    float*  w    = pos2 + HDIM;                        // [32] raw weights

    const int bid  = blockIdx.x;
    const int img  = bid & 63;          // interleave images across waves
    const int tile = bid >> 6;
    const int tid  = threadIdx.x;

    const float res = resolution[img];
    const int   ax  = axis[img];
    const float sig = fmaxf(res * gap[img] * 0.42466090014400953f, 1e-6f);
    const int   R   = (sig < 0.18f) ? 0 : (sig < 0.6f) ? 3 : (sig < 1.4f) ? 7 : 15;

    const int   n_low = (int)fmaxf(floorf(512.0f / res), 1.0f);
    const float nl1   = (float)(n_low - 1);

    if (tid < 31) {
        float e = (float)(tid - 15) / sig;
        w[tid] = expf(-0.5f * e * e);
    }
    for (int i = tid; i < HDIM; i += NT)
        pos2[i] = fminf((float)i / res, nl1);   // true division, as reference

    const int base = tile * TW;
    const size_t ib = (size_t)img * HDIM * HDIM;
    const float* ip = x + ib;
    float*       op = out + ib;

    // ---- load slab into lane-major A (+ reflected halo) ----
    if (ax == 0) {
        const float4* ip4 = (const float4*)ip;
        for (int idx = tid; idx < HDIM * 2; idx += NT) {
            int l4 = idx & 1;
            int p  = idx >> 1;
            float4 v = ip4[p * (HDIM / 4) + (base >> 2) + l4];
            float* dst = A + (4 * l4) * AS + HALO + p;
            dst[0] = v.x; dst[AS] = v.y; dst[2 * AS] = v.z; dst[3 * AS] = v.w;
        }
    } else {
        for (int idx = tid; idx < TW * (HDIM / 4); idx += NT) {
            int v = idx & 127;
            int l = idx >> 7;
            float4 t = *(const float4*)(ip + (size_t)(base + l) * HDIM + 4 * v);
            *(float4*)(A + l * AS + HALO + 4 * v) = t;
        }
    }
    for (int idx = tid; idx < 2 * HALO * TW; idx += NT) {   // 256 halo elems
        int l = idx & (TW - 1);
        int h = idx >> 3;
        int t = (h < HALO) ? (h - HALO) : (HDIM + h - HALO);
        int rt = refl(t);
        float val = (ax == 0) ? ip[rt * HDIM + base + l]
                              : ip[(size_t)(base + l) * HDIM + rt];
        A[l * AS + HALO + t] = val;
    }
    __syncthreads();

    float inv_wsum = 1.0f;
    if (R > 0) {
        float s = 0.f;
        #pragma unroll
        for (int k = 0; k < 31; k++) s += w[k];
        inv_wsum = 1.0f / s;
    }

    // ---- fused blur + downsample -> LOW (fp16) ----
    if      (R == 0)  blur_down<0>(A, LOW, w, inv_wsum, res, n_low, tid);
    else if (R == 3)  blur_down<3>(A, LOW, w, inv_wsum, res, n_low, tid);
    else if (R == 7)  blur_down<7>(A, LOW, w, inv_wsum, res, n_low, tid);
    else              blur_down<15>(A, LOW, w, inv_wsum, res, n_low, tid);
    __syncthreads();

    // ---- upsample + float4 gmem stores ----
    if (ax == 0) {
        for (int idx = tid; idx < HDIM * 2; idx += NT) {
            int l4 = idx & 1;
            int i  = idx >> 1;
            float p2v = pos2[i];
            float l2  = floorf(p2v);
            float f   = p2v - l2;
            int j1 = min((int)l2, n_low - 1);
            int j2 = min(j1 + 1, n_low - 1);
            float omf = 1.0f - f;
            const __half* L0 = LOW + (4 * l4) * LH;
            float4 r;
            r.x = __half2float(L0[j1]) * omf          + __half2float(L0[j2]) * f;
            r.y = __half2float(L0[LH + j1]) * omf     + __half2float(L0[LH + j2]) * f;
            r.z = __half2float(L0[2 * LH + j1]) * omf + __half2float(L0[2 * LH + j2]) * f;
            r.w = __half2float(L0[3 * LH + j1]) * omf + __half2float(L0[3 * LH + j2]) * f;
            *(float4*)(op + i * HDIM + base + 4 * l4) = r;
        }
    } else {
        for (int idx = tid; idx < TW * (HDIM / 4); idx += NT) {
            int v = idx & 127;
            int l = idx >> 7;
            const __half* Lrow = LOW + l * LH;
            const float4 pv = *(const float4*)(pos2 + 4 * v);
            float4 r;
            #pragma unroll
            for (int q = 0; q < 4; q++) {
                float p2v = ((const float*)&pv)[q];
                float l2  = floorf(p2v);
                float f   = p2v - l2;
                int j1 = min((int)l2, n_low - 1);
                int j2 = min(j1 + 1, n_low - 1);
                ((float*)&r)[q] = __half2float(Lrow[j1]) * (1.0f - f)
                                + __half2float(Lrow[j2]) * f;
            }
            *(float4*)(op + (size_t)(base + l) * HDIM + 4 * v) = r;
        }
    }
}

extern "C" void kernel_launch(void* const* d_in, const int* in_sizes, int n_in,
                              void* d_out, int out_size)
{
    const float* x   = (const float*)d_in[0];
    const float* res = (const float*)d_in[1];
    const int*   ax  = (const int*)d_in[2];
    const float* gp  = (const float*)d_in[3];
    float* out = (float*)d_out;

    const int n_img = in_sizes[1];   // 64
    // A(8*548 f32) + LOW(8*520 f16) + pos2(512 f32) + w(32 f32) = 28032 B
    const size_t smem = (size_t)(TW * AS) * 4 + (size_t)(TW * LH) * 2
                      + (size_t)HDIM * 4 + 32 * 4;

    cudaFuncSetAttribute(lowres_kernel,
                         cudaFuncAttributeMaxDynamicSharedMemorySize, (int)smem);

    dim3 grid((HDIM / TW) * n_img);  // 4096 CTAs, image-interleaved
    lowres_kernel<<<grid, NT, smem>>>(x, res, ax, gp, out);
}